// round 2
// baseline (speedup 1.0000x reference)
#include <cuda_runtime.h>
#include <math.h>

// ARIMA sliding-window loss, algebraically collapsed to:
//   err[t] = y[t+33] - K1*FIR(g, win) + (K1*w0 - 1)*mean - K2*std
//   loss   = (sum(y[:33]^2) + sum(err^2)) / S
// Single fused kernel: grid-wide work + last-block final reduction.
// FIR pairs computed with packed fma.rn.f32x2 (Blackwell f32x2 FMA).

#define PW    32
#define T0    33
#define EPSF  1e-5f
#define TPB   256
#define RPT   4
#define TILE  (TPB * RPT)     // 1024 t-values per block
#define MAXB  2048

__device__ double       g_part[MAXB];
__device__ unsigned int g_ctr = 0;   // wraps back to 0 every launch via atomicInc

__device__ __forceinline__ unsigned long long pk2(float a, float b) {
    unsigned long long r;
    asm("mov.b64 %0, {%1, %2};" : "=l"(r) : "f"(a), "f"(b));
    return r;
}
__device__ __forceinline__ void fma2(unsigned long long& acc,
                                     unsigned long long a, unsigned long long b) {
    asm("fma.rn.f32x2 %0, %1, %2, %0;" : "+l"(acc) : "l"(a), "l"(b));
}
__device__ __forceinline__ void upk2(unsigned long long v, float& lo, float& hi) {
    asm("mov.b64 {%0, %1}, %2;" : "=f"(lo), "=f"(hi) : "l"(v));
}
__device__ __forceinline__ float sqrt_apx(float x) {
    float r; asm("sqrt.approx.f32 %0, %1;" : "=f"(r) : "f"(x)); return r;
}

__global__ void __launch_bounds__(TPB) arima_fused(
    const float* __restrict__ y,
    const float* __restrict__ w,
    const float* __restrict__ ab,
    const float* __restrict__ rw_,
    const float* __restrict__ rb_,
    float* __restrict__ out,
    int T, int S)
{
    __shared__ float4 sy4[(TILE + 32) / 4];            // 1056 floats
    float* sy = (float*)sy4;
    __shared__ float  sg[PW];
    __shared__ unsigned long long sgp[PW + 1];         // 33 packed (g[k], g[k-1])
    __shared__ float  sc[3];
    __shared__ double sred[TPB / 32];
    __shared__ int    isLast;

    const int tid = threadIdx.x;
    const int bid = blockIdx.x;
    const int tb  = bid * TILE;

    // FIR coefficients from ar_weight + differencing structure
    if (tid < PW) {
        float wj  = w[tid];
        float wj1 = (tid < PW - 1) ? w[tid + 1] : 0.0f;
        float gv  = wj - wj1;
        if (tid == PW - 2) gv -= 1.0f;   // g[30] = w30 - w31 - 1
        if (tid == PW - 1) gv += 1.0f;   // g[31] = w31 + 1
        sg[tid] = gv;
    }
    if (tid == 0) {
        float rw = rw_[0], rb = rb_[0], b = ab[0], w0 = w[0];
        float denom = rw + EPSF * EPSF;
        float K1 = rw / denom;
        sc[0] = K1;
        sc[1] = (w0 * rb - rb + b) / denom;   // K2
        sc[2] = fmaf(K1, w0, -1.0f);          // M1
    }

    // Stage tile: sy[i] = y[tb+1+i], i in [0, TILE+32)
    for (int i = tid; i < TILE + 32; i += TPB) {
        int gi = tb + 1 + i;
        sy[i] = (gi < S) ? y[gi] : 0.0f;
    }
    __syncthreads();

    // Packed coefficient pairs: sgp[k] = (g[k], g[k-1]), g[-1]=g[32]=0
    if (tid <= PW) {
        float lo = (tid < PW) ? sg[tid] : 0.0f;
        float hi = (tid > 0)  ? sg[tid - 1] : 0.0f;
        sgp[tid] = pk2(lo, hi);
    }
    __syncthreads();

    const float K1 = sc[0], K2 = sc[1], M1 = sc[2];

    // Register window: x[m] = sy[tid*4 + m], m in [0,36)
    float x[36];
    #pragma unroll
    for (int c = 0; c < 9; c++) {
        float4 v = sy4[tid + c];
        x[4*c + 0] = v.x; x[4*c + 1] = v.y; x[4*c + 2] = v.z; x[4*c + 3] = v.w;
    }

    // Packed FIR: acc0 = (fir_t0, fir_t1), acc1 = (fir_t2, fir_t3)
    unsigned long long acc0 = 0ull, acc1 = 0ull;
    #pragma unroll
    for (int k = 0; k <= PW; k++) {
        unsigned long long gpk = sgp[k];
        fma2(acc0, pk2(x[k],     x[k]),     gpk);
        fma2(acc1, pk2(x[k + 2], x[k + 2]), gpk);
    }

    // Packed (sum, sumsq) for the first t
    unsigned long long ssq = 0ull;
    #pragma unroll
    for (int m = 0; m < PW; m++)
        fma2(ssq, pk2(x[m], x[m]), pk2(1.0f, x[m]));

    float fir[RPT], sum, sq;
    upk2(acc0, fir[0], fir[1]);
    upk2(acc1, fir[2], fir[3]);
    upk2(ssq, sum, sq);

    double esum = 0.0;
    const int l0 = tid * RPT;
    #pragma unroll
    for (int r = 0; r < RPT; r++) {
        if (r > 0) {                    // slide the window
            float xn = x[31 + r], xo = x[r - 1];
            sum += xn - xo;
            sq   = fmaf(xn, xn, sq);
            sq   = fmaf(-xo, xo, sq);
        }
        int t = tb + l0 + r;
        if (t < T) {
            float mean = sum * (1.0f / PW);
            float var  = fmaf(-mean, mean, sq * (1.0f / PW));
            float sd   = sqrt_apx(var + EPSF);
            float yt   = x[r + 32];
            float err  = fmaf(-K1, fir[r], yt) + fmaf(M1, mean, -K2 * sd);
            esum += (double)err * (double)err;
        }
    }

    // Block reduction (warp shuffles + smem)
    #pragma unroll
    for (int o = 16; o > 0; o >>= 1)
        esum += __shfl_down_sync(0xffffffffu, esum, o);
    if ((tid & 31) == 0) sred[tid >> 5] = esum;
    __syncthreads();
    if (tid == 0) {
        double bs = 0.0;
        #pragma unroll
        for (int i = 0; i < TPB / 32; i++) bs += sred[i];
        g_part[bid] = bs;
        __threadfence();
        unsigned pos = atomicInc(&g_ctr, gridDim.x - 1);
        isLast = (pos == gridDim.x - 1);
    }
    __syncthreads();

    // Last block: final deterministic reduction + head term
    if (isLast) {
        __threadfence();
        double s = 0.0;
        for (int i = tid; i < (int)gridDim.x; i += TPB) s += g_part[i];
        for (int i = tid; i < T0; i += TPB) { double v = (double)y[i]; s += v * v; }
        #pragma unroll
        for (int o = 16; o > 0; o >>= 1)
            s += __shfl_down_sync(0xffffffffu, s, o);
        if ((tid & 31) == 0) sred[tid >> 5] = s;
        __syncthreads();
        if (tid == 0) {
            double tot = 0.0;
            #pragma unroll
            for (int i = 0; i < TPB / 32; i++) tot += sred[i];
            out[0] = (float)(tot / (double)S);
        }
    }
}

extern "C" void kernel_launch(void* const* d_in, const int* in_sizes, int n_in,
                              void* d_out, int out_size)
{
    const float* y  = (const float*)d_in[0];
    const float* w  = (const float*)d_in[1];
    const float* ab = (const float*)d_in[2];
    const float* rw = (const float*)d_in[3];
    const float* rb = (const float*)d_in[4];
    int S = in_sizes[0];
    int T = S - T0;
    int nblocks = (T + TILE - 1) / TILE;   // S=1M -> 1024 blocks
    if (nblocks > MAXB) nblocks = MAXB;
    arima_fused<<<nblocks, TPB>>>(y, w, ab, rw, rb, (float*)d_out, T, S);
}

// round 3
// speedup vs baseline: 1.1068x; 1.1068x over previous
#include <cuda_runtime.h>
#include <math.h>

// ARIMA sliding-window loss, algebraically collapsed to:
//   err[t] = y[t+33] - K1*FIR(g, win) + (K1*w0 - 1)*mean - K2*std
//   loss   = (sum(y[:33]^2) + sum(err^2)) / S
// One fused kernel. Each thread: 36-float register window -> 4 t-values,
// 4 independent 32-tap FIR chains + O(1) sliding mean/var.

#define PW    32
#define T0    33
#define EPSF  1e-5f
#define TPB   256
#define RPT   4
#define TILE  (TPB * RPT)     // 1024 t-values per block
#define MAXB  2048

__device__ double       g_part[MAXB];
__device__ unsigned int g_ctr = 0;   // atomicInc wraps to 0 each launch

__device__ __forceinline__ float sqrt_apx(float x) {
    float r; asm("sqrt.approx.f32 %0, %1;" : "=f"(r) : "f"(x)); return r;
}

__global__ void __launch_bounds__(TPB, 3) arima_fused(
    const float* __restrict__ y,
    const float* __restrict__ w,
    const float* __restrict__ ab,
    const float* __restrict__ rw_,
    const float* __restrict__ rb_,
    float* __restrict__ out,
    int T, int S)
{
    __shared__ float4 sy4[(TILE + 32) / 4];   // 1056 floats: y[tb+1 .. tb+1056]
    float* sy = (float*)sy4;
    __shared__ float  sg[PW];
    __shared__ float  sc[3];
    __shared__ double sred[TPB / 32];
    __shared__ int    isLast;

    const int tid = threadIdx.x;
    const int bid = blockIdx.x;
    const int tb  = bid * TILE;

    // FIR taps from ar_weight + differencing structure
    if (tid < PW) {
        float wj  = w[tid];
        float wj1 = (tid < PW - 1) ? w[tid + 1] : 0.0f;
        float gv  = wj - wj1;
        if (tid == PW - 2) gv -= 1.0f;   // g[30] = w30 - w31 - 1
        if (tid == PW - 1) gv += 1.0f;   // g[31] = w31 + 1
        sg[tid] = gv;
    }
    if (tid == 0) {
        float rw = rw_[0], rb = rb_[0], b = ab[0], w0 = w[0];
        float denom = rw + EPSF * EPSF;
        float K1 = rw / denom;
        sc[0] = K1;
        sc[1] = (w0 * rb - rb + b) / denom;   // K2
        sc[2] = fmaf(K1, w0, -1.0f);          // M1 = K1*w0 - 1
    }

    // Stage tile: sy[i] = y[tb+1+i]
    #pragma unroll
    for (int c = 0; c < 5; c++) {
        int i = tid + c * TPB;
        if (i < TILE + 32) {
            int gi = tb + 1 + i;
            sy[i] = (gi < S) ? y[gi] : 0.0f;
        }
    }
    __syncthreads();

    const float K1 = sc[0], K2 = sc[1], M1 = sc[2];

    // Register window: x[m] = sy[tid*4 + m], m in [0,36). 9 x LDS.128.
    float x[36];
    #pragma unroll
    for (int c = 0; c < 9; c++) {
        float4 v = sy4[tid + c];
        x[4*c + 0] = v.x; x[4*c + 1] = v.y; x[4*c + 2] = v.z; x[4*c + 3] = v.w;
    }

    // 4 independent FIR chains + initial sum/sumsq
    float f0 = 0.f, f1 = 0.f, f2 = 0.f, f3 = 0.f;
    float sum = 0.f, sq = 0.f;
    #pragma unroll
    for (int j = 0; j < PW; j++) {
        float gj = sg[j];
        f0 = fmaf(gj, x[j],     f0);
        f1 = fmaf(gj, x[j + 1], f1);
        f2 = fmaf(gj, x[j + 2], f2);
        f3 = fmaf(gj, x[j + 3], f3);
        sum += x[j];
        sq  = fmaf(x[j], x[j], sq);
    }
    float fir[RPT] = {f0, f1, f2, f3};

    float esum_f = 0.0f;
    const int l0 = tid * RPT;
    #pragma unroll
    for (int r = 0; r < RPT; r++) {
        if (r > 0) {                        // slide the window stats
            float xn = x[31 + r], xo = x[r - 1];
            sum += xn - xo;
            sq   = fmaf(xn, xn, sq);
            sq   = fmaf(-xo, xo, sq);
        }
        int t = tb + l0 + r;
        if (t < T) {
            float mean = sum * (1.0f / PW);
            float var  = fmaf(-mean, mean, sq * (1.0f / PW));
            float sd   = sqrt_apx(var + EPSF);
            float yt   = x[r + 32];
            float err  = fmaf(-K1, fir[r], yt) + fmaf(M1, mean, -K2 * sd);
            esum_f = fmaf(err, err, esum_f);
        }
    }

    // Warp/block reduction (double from warp level up)
    double esum = (double)esum_f;
    #pragma unroll
    for (int o = 16; o > 0; o >>= 1)
        esum += __shfl_down_sync(0xffffffffu, esum, o);
    if ((tid & 31) == 0) sred[tid >> 5] = esum;
    __syncthreads();
    if (tid == 0) {
        double bs = 0.0;
        #pragma unroll
        for (int i = 0; i < TPB / 32; i++) bs += sred[i];
        g_part[bid] = bs;
        __threadfence();
        unsigned pos = atomicInc(&g_ctr, gridDim.x - 1);
        isLast = (pos == gridDim.x - 1);
    }
    __syncthreads();

    // Last block: deterministic final reduction + head term
    if (isLast) {
        __threadfence();
        double s = 0.0;
        for (int i = tid; i < (int)gridDim.x; i += TPB) s += g_part[i];
        for (int i = tid; i < T0; i += TPB) { double v = (double)y[i]; s += v * v; }
        #pragma unroll
        for (int o = 16; o > 0; o >>= 1)
            s += __shfl_down_sync(0xffffffffu, s, o);
        if ((tid & 31) == 0) sred[tid >> 5] = s;
        __syncthreads();
        if (tid == 0) {
            double tot = 0.0;
            #pragma unroll
            for (int i = 0; i < TPB / 32; i++) tot += sred[i];
            out[0] = (float)(tot / (double)S);
        }
    }
}

extern "C" void kernel_launch(void* const* d_in, const int* in_sizes, int n_in,
                              void* d_out, int out_size)
{
    const float* y  = (const float*)d_in[0];
    const float* w  = (const float*)d_in[1];
    const float* ab = (const float*)d_in[2];
    const float* rw = (const float*)d_in[3];
    const float* rb = (const float*)d_in[4];
    int S = in_sizes[0];
    int T = S - T0;
    int nblocks = (T + TILE - 1) / TILE;   // S=1M -> 1024 blocks
    if (nblocks > MAXB) nblocks = MAXB;
    arima_fused<<<nblocks, TPB>>>(y, w, ab, rw, rb, (float*)d_out, T, S);
}

// round 4
// speedup vs baseline: 1.4047x; 1.2691x over previous
#include <cuda_runtime.h>
#include <math.h>

// ARIMA sliding-window loss, algebraically collapsed to:
//   err[t] = y[t+33] - K1*FIR(g, win) + (K1*w0 - 1)*mean - K2*std
//   loss   = (sum(y[:33]^2) + sum(err^2)) / S
// One fused kernel, last-block final reduction.
// Per thread: 36-float register window (9x LDS.128), coefficients via 8x LDS.128.

#define PW    32
#define T0    33
#define EPSF  1e-5f
#define TPB   128
#define RPT   4
#define TILE  (TPB * RPT)     // 512 t-values per block
#define MAXB  4096

__device__ double       g_part[MAXB];
__device__ unsigned int g_ctr = 0;   // atomicInc wraps to 0 each launch

__device__ __forceinline__ float sqrt_apx(float x) {
    float r; asm("sqrt.approx.f32 %0, %1;" : "=f"(r) : "f"(x)); return r;
}

__global__ void __launch_bounds__(TPB) arima_fused(
    const float* __restrict__ y,
    const float* __restrict__ w,
    const float* __restrict__ ab,
    const float* __restrict__ rw_,
    const float* __restrict__ rb_,
    float* __restrict__ out,
    int T, int S)
{
    // sy[k] = y[tb+1+k]; padded so 9 LDS.128 per thread stay in-bounds
    __shared__ __align__(16) float sy[TILE + 40];
    __shared__ __align__(16) float sg[PW];
    __shared__ float  sc[3];
    __shared__ double sred[TPB / 32];
    __shared__ int    isLast;

    const float4* sy4 = (const float4*)sy;
    const float4* sg4 = (const float4*)sg;

    const int tid = threadIdx.x;
    const int bid = blockIdx.x;
    const int tb  = bid * TILE;          // TILE%4==0 -> y4 base aligned

    // FIR taps from ar_weight + differencing structure
    if (tid < PW) {
        float wj  = w[tid];
        float wj1 = (tid < PW - 1) ? w[tid + 1] : 0.0f;
        float gv  = wj - wj1;
        if (tid == PW - 2) gv -= 1.0f;   // g[30] = w30 - w31 - 1
        if (tid == PW - 1) gv += 1.0f;   // g[31] = w31 + 1
        sg[tid] = gv;
    }
    if (tid == 0) {
        float rw = rw_[0], rb = rb_[0], b = ab[0], w0 = w[0];
        float denom = rw + EPSF * EPSF;
        float K1 = rw / denom;
        sc[0] = K1;
        sc[1] = (w0 * rb - rb + b) / denom;   // K2
        sc[2] = fmaf(K1, w0, -1.0f);          // M1 = K1*w0 - 1
        sy[TILE + 36] = 0.f; sy[TILE + 37] = 0.f;
        sy[TILE + 38] = 0.f; sy[TILE + 39] = 0.f;
    }

    // Stage: aligned vector loads of y[tb + 4i .. +3], scalar-scatter with +1 shift
    // sy[4i-1+d] = y[tb+4i+d]. Need k up to TILE+35 -> i up to TILE/4+9.
    {
        const float4* y4 = (const float4*)y;
        #pragma unroll
        for (int it = 0; it < 2; it++) {
            int i = tid + it * TPB;
            if (i < TILE / 4 + 10) {
                int gf = tb + 4 * i;                   // global float index of v.x
                float4 v;
                if (gf + 3 < S) v = y4[(tb >> 2) + i];
                else {
                    v.x = (gf     < S) ? y[gf]     : 0.f;
                    v.y = (gf + 1 < S) ? y[gf + 1] : 0.f;
                    v.z = (gf + 2 < S) ? y[gf + 2] : 0.f;
                    v.w = (gf + 3 < S) ? y[gf + 3] : 0.f;
                }
                int k0 = 4 * i - 1;
                if (k0 >= 0) sy[k0] = v.x;
                sy[k0 + 1] = v.y;
                sy[k0 + 2] = v.z;
                sy[k0 + 3] = v.w;
            }
        }
    }
    __syncthreads();

    const float K1 = sc[0], K2 = sc[1], M1 = sc[2];

    // Register window: x[m] = sy[4*tid + m], m in [0,36). 9 x LDS.128 (aligned).
    float x[36];
    #pragma unroll
    for (int c = 0; c < 9; c++) {
        float4 v = sy4[tid + c];
        x[4*c + 0] = v.x; x[4*c + 1] = v.y; x[4*c + 2] = v.z; x[4*c + 3] = v.w;
    }

    // 4 FIR chains + sum/sumsq over x[0..31]; coefficients 4-at-a-time
    float f0 = 0.f, f1 = 0.f, f2 = 0.f, f3 = 0.f;
    float sum = 0.f, sq = 0.f;
    #pragma unroll
    for (int c = 0; c < 8; c++) {
        float4 gc = sg4[c];
        const int j = 4 * c;
        f0 = fmaf(gc.x, x[j],     f0); f1 = fmaf(gc.x, x[j + 1], f1);
        f2 = fmaf(gc.x, x[j + 2], f2); f3 = fmaf(gc.x, x[j + 3], f3);
        f0 = fmaf(gc.y, x[j + 1], f0); f1 = fmaf(gc.y, x[j + 2], f1);
        f2 = fmaf(gc.y, x[j + 3], f2); f3 = fmaf(gc.y, x[j + 4], f3);
        f0 = fmaf(gc.z, x[j + 2], f0); f1 = fmaf(gc.z, x[j + 3], f1);
        f2 = fmaf(gc.z, x[j + 4], f2); f3 = fmaf(gc.z, x[j + 5], f3);
        f0 = fmaf(gc.w, x[j + 3], f0); f1 = fmaf(gc.w, x[j + 4], f1);
        f2 = fmaf(gc.w, x[j + 5], f2); f3 = fmaf(gc.w, x[j + 6], f3);
        sum += x[j] + x[j + 1] + x[j + 2] + x[j + 3];
        sq = fmaf(x[j],     x[j],     sq);
        sq = fmaf(x[j + 1], x[j + 1], sq);
        sq = fmaf(x[j + 2], x[j + 2], sq);
        sq = fmaf(x[j + 3], x[j + 3], sq);
    }
    float fir[RPT] = {f0, f1, f2, f3};

    float esum_f = 0.0f;
    const int l0 = tid * RPT;
    #pragma unroll
    for (int r = 0; r < RPT; r++) {
        if (r > 0) {                        // slide window stats
            float xn = x[31 + r], xo = x[r - 1];
            sum += xn - xo;
            sq   = fmaf(xn, xn, sq);
            sq   = fmaf(-xo, xo, sq);
        }
        int t = tb + l0 + r;
        if (t < T) {
            float mean = sum * (1.0f / PW);
            float var  = fmaf(-mean, mean, sq * (1.0f / PW));
            float sd   = sqrt_apx(var + EPSF);
            float yt   = x[r + 32];
            float err  = fmaf(-K1, fir[r], yt) + fmaf(M1, mean, -K2 * sd);
            esum_f = fmaf(err, err, esum_f);
        }
    }

    // Block reduction (double from warp level up)
    double esum = (double)esum_f;
    #pragma unroll
    for (int o = 16; o > 0; o >>= 1)
        esum += __shfl_down_sync(0xffffffffu, esum, o);
    if ((tid & 31) == 0) sred[tid >> 5] = esum;
    __syncthreads();
    if (tid == 0) {
        double bs = 0.0;
        #pragma unroll
        for (int i = 0; i < TPB / 32; i++) bs += sred[i];
        g_part[bid] = bs;
        __threadfence();
        unsigned pos = atomicInc(&g_ctr, gridDim.x - 1);
        isLast = (pos == gridDim.x - 1);
    }
    __syncthreads();

    // Last block: deterministic final reduction + head term
    if (isLast) {
        __threadfence();
        double s = 0.0;
        for (int i = tid; i < (int)gridDim.x; i += TPB) s += g_part[i];
        for (int i = tid; i < T0; i += TPB) { double v = (double)y[i]; s += v * v; }
        #pragma unroll
        for (int o = 16; o > 0; o >>= 1)
            s += __shfl_down_sync(0xffffffffu, s, o);
        if ((tid & 31) == 0) sred[tid >> 5] = s;
        __syncthreads();
        if (tid == 0) {
            double tot = 0.0;
            #pragma unroll
            for (int i = 0; i < TPB / 32; i++) tot += sred[i];
            out[0] = (float)(tot / (double)S);
        }
    }
}

extern "C" void kernel_launch(void* const* d_in, const int* in_sizes, int n_in,
                              void* d_out, int out_size)
{
    const float* y  = (const float*)d_in[0];
    const float* w  = (const float*)d_in[1];
    const float* ab = (const float*)d_in[2];
    const float* rw = (const float*)d_in[3];
    const float* rb = (const float*)d_in[4];
    int S = in_sizes[0];
    int T = S - T0;
    int nblocks = (T + TILE - 1) / TILE;   // S=1M -> 2048 blocks
    if (nblocks > MAXB) nblocks = MAXB;
    arima_fused<<<nblocks, TPB>>>(y, w, ab, rw, rb, (float*)d_out, T, S);
}

// round 5
// speedup vs baseline: 1.4320x; 1.0194x over previous
#include <cuda_runtime.h>
#include <math.h>

// ARIMA sliding-window loss, algebraically collapsed to:
//   err[t] = y[t+33] - K1*FIR(g, win) + (K1*w0 - 1)*mean - K2*std
//   loss   = (sum(y[:33]^2) + sum(err^2)) / S
// Direct-gmem version: no staging, no block barrier in the hot path.
// Each thread: 44-float register window (11x LDG.128) -> 8 t-values,
// 8 independent 32-tap FIR chains + O(1) sliding mean/var.

#define PW    32
#define T0    33
#define EPSF  1e-5f
#define TPB   128
#define RPT   8
#define TILE  (TPB * RPT)     // 1024 t-values per block
#define MAXB  2048

__device__ double       g_part[MAXB];
__device__ unsigned int g_ctr = 0;   // atomicInc wraps to 0 each launch

__device__ __forceinline__ float sqrt_apx(float x) {
    float r; asm("sqrt.approx.f32 %0, %1;" : "=f"(r) : "f"(x)); return r;
}

__global__ void __launch_bounds__(TPB, 6) arima_fused(
    const float* __restrict__ y,
    const float* __restrict__ w,
    const float* __restrict__ ab,
    const float* __restrict__ rw_,
    const float* __restrict__ rb_,
    float* __restrict__ out,
    int T, int S)
{
    __shared__ __align__(16) float sg[PW];
    __shared__ float  sc[3];
    __shared__ double sred[TPB / 32];
    __shared__ int    isLast;

    const float4* sg4 = (const float4*)sg;
    const int tid = threadIdx.x;
    const int bid = blockIdx.x;

    // FIR taps from ar_weight + differencing structure
    if (tid < PW) {
        float wj  = w[tid];
        float wj1 = (tid < PW - 1) ? w[tid + 1] : 0.0f;
        float gv  = wj - wj1;
        if (tid == PW - 2) gv -= 1.0f;   // g[30] = w30 - w31 - 1
        if (tid == PW - 1) gv += 1.0f;   // g[31] = w31 + 1
        sg[tid] = gv;
    }
    if (tid == 0) {
        float rw = rw_[0], rb = rb_[0], b = ab[0], w0 = w[0];
        float denom = rw + EPSF * EPSF;
        float K1 = rw / denom;
        sc[0] = K1;
        sc[1] = (w0 * rb - rb + b) / denom;   // K2
        sc[2] = fmaf(K1, w0, -1.0f);          // M1 = K1*w0 - 1
    }
    __syncthreads();

    const float K1 = sc[0], K2 = sc[1], M1 = sc[2];

    // Per-thread window: xv[m] = y[t0 + m], m in [0,44). t0 % 8 == 0 -> aligned.
    const int t0 = (bid * TPB + tid) * RPT;
    float xv[44];
    if (t0 + 44 <= S) {
        const float4* y4 = (const float4*)(y + t0);
        #pragma unroll
        for (int c = 0; c < 11; c++) {
            float4 v = y4[c];
            xv[4*c + 0] = v.x; xv[4*c + 1] = v.y;
            xv[4*c + 2] = v.z; xv[4*c + 3] = v.w;
        }
    } else {
        #pragma unroll
        for (int m = 0; m < 44; m++)
            xv[m] = (t0 + m < S) ? y[t0 + m] : 0.0f;
    }

    // 8 FIR chains + sum/sumsq over xv[1..32] (window of t0)
    float f[RPT];
    #pragma unroll
    for (int r = 0; r < RPT; r++) f[r] = 0.0f;
    float sum = 0.f, sq = 0.f;
    #pragma unroll
    for (int c = 0; c < 8; c++) {
        float4 gc = sg4[c];
        const float ge[4] = {gc.x, gc.y, gc.z, gc.w};
        #pragma unroll
        for (int e = 0; e < 4; e++) {
            const int j = 4 * c + e;
            float xj = xv[1 + j];
            sum += xj;
            sq   = fmaf(xj, xj, sq);
            #pragma unroll
            for (int r = 0; r < RPT; r++)
                f[r] = fmaf(ge[e], xv[1 + j + r], f[r]);
        }
    }

    float esum_f = 0.0f;
    #pragma unroll
    for (int r = 0; r < RPT; r++) {
        if (r > 0) {                        // slide window stats
            float xn = xv[32 + r], xo = xv[r];
            sum += xn - xo;
            sq   = fmaf(xn, xn, sq);
            sq   = fmaf(-xo, xo, sq);
        }
        if (t0 + r < T) {
            float mean = sum * (1.0f / PW);
            float var  = fmaf(-mean, mean, sq * (1.0f / PW));
            float sd   = sqrt_apx(var + EPSF);
            float yt   = xv[33 + r];
            float err  = fmaf(-K1, f[r], yt) + fmaf(M1, mean, -K2 * sd);
            esum_f = fmaf(err, err, esum_f);
        }
    }

    // Block reduction (double from warp level up)
    double esum = (double)esum_f;
    #pragma unroll
    for (int o = 16; o > 0; o >>= 1)
        esum += __shfl_down_sync(0xffffffffu, esum, o);
    if ((tid & 31) == 0) sred[tid >> 5] = esum;
    __syncthreads();
    if (tid == 0) {
        double bs = 0.0;
        #pragma unroll
        for (int i = 0; i < TPB / 32; i++) bs += sred[i];
        g_part[bid] = bs;
        __threadfence();
        unsigned pos = atomicInc(&g_ctr, gridDim.x - 1);
        isLast = (pos == gridDim.x - 1);
    }
    __syncthreads();

    // Last block: deterministic final reduction + head term
    if (isLast) {
        __threadfence();
        double s = 0.0;
        for (int i = tid; i < (int)gridDim.x; i += TPB) s += g_part[i];
        for (int i = tid; i < T0; i += TPB) { double v = (double)y[i]; s += v * v; }
        #pragma unroll
        for (int o = 16; o > 0; o >>= 1)
            s += __shfl_down_sync(0xffffffffu, s, o);
        if ((tid & 31) == 0) sred[tid >> 5] = s;
        __syncthreads();
        if (tid == 0) {
            double tot = 0.0;
            #pragma unroll
            for (int i = 0; i < TPB / 32; i++) tot += sred[i];
            out[0] = (float)(tot / (double)S);
        }
    }
}

extern "C" void kernel_launch(void* const* d_in, const int* in_sizes, int n_in,
                              void* d_out, int out_size)
{
    const float* y  = (const float*)d_in[0];
    const float* w  = (const float*)d_in[1];
    const float* ab = (const float*)d_in[2];
    const float* rw = (const float*)d_in[3];
    const float* rb = (const float*)d_in[4];
    int S = in_sizes[0];
    int T = S - T0;
    int nblocks = (T + TILE - 1) / TILE;   // S=1M -> 1024 blocks
    if (nblocks > MAXB) nblocks = MAXB;
    arima_fused<<<nblocks, TPB>>>(y, w, ab, rw, rb, (float*)d_out, T, S);
}

// round 6
// speedup vs baseline: 1.6617x; 1.1604x over previous
#include <cuda_runtime.h>
#include <math.h>

// ARIMA sliding-window loss, algebraically collapsed to:
//   err[t] = y[t+33] - K1*FIR(g, win) + M1q*sum(win) - K2q*sqrt(32*sumsq - sum^2 + 1024*eps)
//   loss   = (sum(y[:33]^2) + sum(err^2)) / S
// Block stages a coalesced tile in smem; each thread takes a 44-float register
// window (11 aligned LDS.128) and produces 8 consecutive t-values:
// 8 independent 32-tap FIR chains + O(1) sliding sum/sumsq.

#define PW    32
#define T0    33
#define EPSF  1e-5f
#define TPB   128
#define RPT   8
#define TILE  (TPB * RPT)        // 1024 t per block
#define STAGE (TILE + 44)        // y[tb .. tb+STAGE)
#define MAXB  2048

__device__ double       g_part[MAXB];
__device__ unsigned int g_ctr = 0;   // atomicInc wraps to 0 each launch

__device__ __forceinline__ float sqrt_apx(float x) {
    float r; asm("sqrt.approx.f32 %0, %1;" : "=f"(r) : "f"(x)); return r;
}

__global__ void __launch_bounds__(TPB, 7) arima_fused(
    const float* __restrict__ y,
    const float* __restrict__ w,
    const float* __restrict__ ab,
    const float* __restrict__ rw_,
    const float* __restrict__ rb_,
    float* __restrict__ out,
    int T, int S)
{
    __shared__ __align__(16) float sy[STAGE];     // 1068 floats
    __shared__ __align__(16) float sg[PW];
    __shared__ float  sc[3];
    __shared__ double sred[TPB / 32];
    __shared__ int    isLast;

    const float4* sy4 = (const float4*)sy;
    const float4* sg4 = (const float4*)sg;
    const int tid = threadIdx.x;
    const int bid = blockIdx.x;
    const int tb  = bid * TILE;

    // FIR taps from ar_weight + differencing structure
    if (tid < PW) {
        float wj  = w[tid];
        float wj1 = (tid < PW - 1) ? w[tid + 1] : 0.0f;
        float gv  = wj - wj1;
        if (tid == PW - 2) gv -= 1.0f;   // g[30] = w30 - w31 - 1
        if (tid == PW - 1) gv += 1.0f;   // g[31] = w31 + 1
        sg[tid] = gv;
    }
    if (tid == 0) {
        float rw = rw_[0], rb = rb_[0], b = ab[0], w0 = w[0];
        float denom = rw + EPSF * EPSF;
        float K1 = rw / denom;
        float K2 = (w0 * rb - rb + b) / denom;
        float M1 = fmaf(K1, w0, -1.0f);
        sc[0] = K1;
        sc[1] = K2 * (1.0f / 32.0f);      // K2q
        sc[2] = M1 * (1.0f / 32.0f);      // M1q
    }

    // Coalesced stage: sy[i] = y[tb+i], aligned float4 (tb % 1024 == 0)
    {
        const float4* y4 = (const float4*)(y + tb);
        #pragma unroll
        for (int c = 0; c < 3; c++) {
            int i = tid + c * TPB;                 // float4 index
            if (i < (STAGE >> 2)) {
                int gf = tb + 4 * i;
                float4 v;
                if (gf + 3 < S) v = y4[i];
                else {
                    v.x = (gf     < S) ? y[gf]     : 0.f;
                    v.y = (gf + 1 < S) ? y[gf + 1] : 0.f;
                    v.z = (gf + 2 < S) ? y[gf + 2] : 0.f;
                    v.w = (gf + 3 < S) ? y[gf + 3] : 0.f;
                }
                ((float4*)sy)[i] = v;
            }
        }
    }
    __syncthreads();

    const float K1 = sc[0], K2q = sc[1], M1q = sc[2];
    const float C0 = 1024.0f * EPSF;

    // Register window: xv[m] = sy[8*tid + m] = y[t0+m], m in [0,44). Aligned LDS.128.
    const int t0 = tb + tid * RPT;
    float xv[44];
    #pragma unroll
    for (int c = 0; c < 11; c++) {
        float4 v = sy4[2 * tid + c];
        xv[4*c + 0] = v.x; xv[4*c + 1] = v.y;
        xv[4*c + 2] = v.z; xv[4*c + 3] = v.w;
    }

    // 8 FIR chains over xv[1+r .. 32+r] + initial sum/sumsq over xv[1..32]
    float f[RPT];
    #pragma unroll
    for (int r = 0; r < RPT; r++) f[r] = 0.0f;
    float sum = 0.f, sq = 0.f;
    #pragma unroll
    for (int c = 0; c < 8; c++) {
        float4 gc = sg4[c];
        const float ge[4] = {gc.x, gc.y, gc.z, gc.w};
        #pragma unroll
        for (int e = 0; e < 4; e++) {
            const int j = 4 * c + e;
            float xj = xv[1 + j];
            sum += xj;
            sq   = fmaf(xj, xj, sq);
            #pragma unroll
            for (int r = 0; r < RPT; r++)
                f[r] = fmaf(ge[e], xv[1 + j + r], f[r]);
        }
    }

    float esum_f = 0.0f;
    if (t0 + RPT <= T) {                 // interior: no per-r bound checks
        #pragma unroll
        for (int r = 0; r < RPT; r++) {
            if (r > 0) {
                float xn = xv[32 + r], xo = xv[r];
                sum += xn - xo;
                sq   = fmaf(xn, xn, sq);
                sq   = fmaf(-xo, xo, sq);
            }
            float u   = fmaf(-sum, sum, 32.0f * sq);
            float sd  = sqrt_apx(u + C0);
            float err = fmaf(-K2q, sd, fmaf(M1q, sum, fmaf(-K1, f[r], xv[33 + r])));
            esum_f = fmaf(err, err, esum_f);
        }
    } else {
        #pragma unroll
        for (int r = 0; r < RPT; r++) {
            if (r > 0) {
                float xn = xv[32 + r], xo = xv[r];
                sum += xn - xo;
                sq   = fmaf(xn, xn, sq);
                sq   = fmaf(-xo, xo, sq);
            }
            if (t0 + r < T) {
                float u   = fmaf(-sum, sum, 32.0f * sq);
                float sd  = sqrt_apx(u + C0);
                float err = fmaf(-K2q, sd, fmaf(M1q, sum, fmaf(-K1, f[r], xv[33 + r])));
                esum_f = fmaf(err, err, esum_f);
            }
        }
    }

    // Block reduction (double from warp level up)
    double esum = (double)esum_f;
    #pragma unroll
    for (int o = 16; o > 0; o >>= 1)
        esum += __shfl_down_sync(0xffffffffu, esum, o);
    if ((tid & 31) == 0) sred[tid >> 5] = esum;
    __syncthreads();
    if (tid == 0) {
        double bs = 0.0;
        #pragma unroll
        for (int i = 0; i < TPB / 32; i++) bs += sred[i];
        g_part[bid] = bs;
        __threadfence();
        unsigned pos = atomicInc(&g_ctr, gridDim.x - 1);
        isLast = (pos == gridDim.x - 1);
    }
    __syncthreads();

    // Last block: deterministic final reduction + head term
    if (isLast) {
        __threadfence();
        double s = 0.0;
        for (int i = tid; i < (int)gridDim.x; i += TPB) s += g_part[i];
        for (int i = tid; i < T0; i += TPB) { double v = (double)y[i]; s += v * v; }
        #pragma unroll
        for (int o = 16; o > 0; o >>= 1)
            s += __shfl_down_sync(0xffffffffu, s, o);
        if ((tid & 31) == 0) sred[tid >> 5] = s;
        __syncthreads();
        if (tid == 0) {
            double tot = 0.0;
            #pragma unroll
            for (int i = 0; i < TPB / 32; i++) tot += sred[i];
            out[0] = (float)(tot / (double)S);
        }
    }
}

extern "C" void kernel_launch(void* const* d_in, const int* in_sizes, int n_in,
                              void* d_out, int out_size)
{
    const float* y  = (const float*)d_in[0];
    const float* w  = (const float*)d_in[1];
    const float* ab = (const float*)d_in[2];
    const float* rw = (const float*)d_in[3];
    const float* rb = (const float*)d_in[4];
    int S = in_sizes[0];
    int T = S - T0;
    int nblocks = (T + TILE - 1) / TILE;   // S=1M -> 1024 blocks, fully resident
    if (nblocks > MAXB) nblocks = MAXB;
    arima_fused<<<nblocks, TPB>>>(y, w, ab, rw, rb, (float*)d_out, T, S);
}